// round 3
// baseline (speedup 1.0000x reference)
#include <cuda_runtime.h>
#include <math.h>
#include <stdint.h>

#define HFD 64
#define WFD 64
#define CIN 1280
#define CCAP 256
#define NCAPS 19
#define DK 64
#define DV 16
#define NP 48              // 0..18 score-base, 19 act-logit, 20..35 V, 36..47 zero pad
#define BATCH 8
#define NINST 32
#define NPTS 256
#define NPIX (HFD*WFD)     // 4096

// ---- device scratch (no cudaMalloc allowed) ----
__device__ float    g_QW[NCAPS*258];          // 0.125 * Q @ Wk^T   [19,258]
__device__ float    g_W2[CCAP*NP];            // fold RHS [256 x 48]
__device__ uint32_t g_Wf_hi[CIN*NP];          // folded weights, tf32 hi
__device__ uint32_t g_Wf_lo[CIN*NP];          // tf32 lo residual
__device__ float    g_const[NP];
__device__ float    g_pk[BATCH*NPIX*NP];      // 6.3 MB

__device__ __forceinline__ uint32_t f2tf32(float x) {
    uint32_t r; asm("cvt.rna.tf32.f32 %0, %1;" : "=r"(r) : "f"(x)); return r;
}

// ================= prep: QW = 0.125*Q@Wk^T, W2 operand, folded biases (1 block) =================
__global__ __launch_bounds__(256) void prep_kernel(
    const float* __restrict__ Q,  const float* __restrict__ Wk,
    const float* __restrict__ Wv, const float* __restrict__ bp,
    const float* __restrict__ ba, const float* __restrict__ bk,
    const float* __restrict__ bv)
{
    int t = threadIdx.x;
    // QW [19 x 258]
    for (int idx = t; idx < NCAPS*258; idx += 256) {
        int c = idx / 258, j = idx % 258;
        float s = 0.f;
        #pragma unroll 8
        for (int o = 0; o < DK; ++o) s += Q[c*DK + o] * Wk[j*DK + o];
        g_QW[idx] = 0.125f * s;
    }
    __syncthreads();
    // W2 [256 x 48]: col<19 -> QW[col][j]; 20..35 -> Wv[j][col-20]; else 0
    for (int idx = t; idx < CCAP*NP; idx += 256) {
        int j = idx / NP, col = idx % NP;
        float v = 0.f;
        if (col < NCAPS) v = g_QW[col*258 + j];
        else if (col >= 20 && col < 20 + DV) v = Wv[j*DV + (col - 20)];
        g_W2[idx] = v;
    }
    // folded biases
    if (t < NP) {
        float s = 0.f;
        if (t < NCAPS) {
            for (int j = 0; j < CCAP; ++j) s += bp[j] * g_QW[t*258 + j];
            float qb = 0.f;
            for (int o = 0; o < DK; ++o) qb += Q[t*DK + o] * bk[o];
            s += 0.125f * qb;
        } else if (t == NCAPS) {
            s = ba[0];
        } else if (t < 20 + DV) {
            int o = t - 20;
            s = bv[o];
            for (int j = 0; j < CCAP; ++j) s += bp[j] * Wv[j*DV + o];
        }
        g_const[t] = s;
    }
}

// ================= fold: Wf[1280 x 48] = Wp^T[1280 x 256] @ W2[256 x 48], tf32-split =================
// grid 20 (64 c each), 256 threads = 64 c_local x 4 tq (each tq covers 12 cols)
__global__ __launch_bounds__(256) void fold_kernel(const float* __restrict__ Wp,
                                                   const float* __restrict__ Wa) {
    __shared__ float wpS[64*64];   // [j][c] tile
    __shared__ float w2S[64*NP];   // [j][col] tile
    int t = threadIdx.x;
    int c0 = blockIdx.x * 64;
    int cl = t & 63;
    int tq = t >> 6;
    float acc[12];
    #pragma unroll
    for (int r = 0; r < 12; ++r) acc[r] = 0.f;

    for (int j0 = 0; j0 < CCAP; j0 += 64) {
        // load Wp tile: Wp[j0+jj][c0 + c], coalesced rows
        #pragma unroll
        for (int r = 0; r < 4; ++r) {
            int i = t + 256*r;               // 1024 float4
            int jj = i >> 4, c4 = (i & 15) * 4;
            *(float4*)&wpS[jj*64 + c4] = *(const float4*)&Wp[(size_t)(j0+jj)*CIN + c0 + c4];
        }
        #pragma unroll
        for (int r = 0; r < 3; ++r) {
            int i = t + 256*r;               // 768 float4
            int jj = i / 12, c4 = (i % 12) * 4;
            *(float4*)&w2S[jj*NP + c4] = *(const float4*)&g_W2[(j0+jj)*NP + c4];
        }
        __syncthreads();
        #pragma unroll 4
        for (int jj = 0; jj < 64; ++jj) {
            float a = wpS[jj*64 + cl];
            #pragma unroll
            for (int r = 0; r < 12; ++r)
                acc[r] += a * w2S[jj*NP + tq*12 + r];
        }
        __syncthreads();
    }
    int c = c0 + cl;
    #pragma unroll
    for (int r = 0; r < 12; ++r) {
        int col = tq*12 + r;
        float s = (col == NCAPS) ? Wa[c] : acc[r];
        uint32_t hi = f2tf32(s);
        float lo = s - __uint_as_float(hi);
        g_Wf_hi[c*NP + col] = hi;
        g_Wf_lo[c*NP + col] = f2tf32(lo);
    }
}

// ================= GEMM: pk[32768 x 48] = feat @ Wfold, 3xTF32 mma, 3-stage cp.async =================
#define BM 128
#define BK 16
#define AS_STRIDE 136
#define BS_STRIDE 56
#define NKCH (CIN/BK)      // 80

#define CP_ASYNC16(dst_s32, src) \
    asm volatile("cp.async.cg.shared.global [%0], [%1], 16;\n" :: "r"(dst_s32), "l"(src))
#define CP_COMMIT() asm volatile("cp.async.commit_group;\n")

__device__ __forceinline__ void mma_tf32(float* d, const uint32_t* a, uint32_t b0, uint32_t b1) {
    asm volatile(
        "mma.sync.aligned.m16n8k8.row.col.f32.tf32.tf32.f32 "
        "{%0,%1,%2,%3},{%4,%5,%6,%7},{%8,%9},{%0,%1,%2,%3};\n"
        : "+f"(d[0]), "+f"(d[1]), "+f"(d[2]), "+f"(d[3])
        : "r"(a[0]), "r"(a[1]), "r"(a[2]), "r"(a[3]), "r"(b0), "r"(b1));
}

// smem floats: As 3x(16x136)=6528 | Bhi 3x896 @6528 | Blo 3x896 @9216 | csts 48 @11904
// epilogue: Cs 128x48=6144 reuses [0,6144)
__global__ __launch_bounds__(512, 2) void gemm_kernel(const float* __restrict__ feat) {
    __shared__ __align__(16) float smem[11952];
    int t = threadIdx.x;
    int m0 = blockIdx.x * BM;
    int b  = m0 / NPIX;
    int pix0 = m0 % NPIX;
    const float* aBase = feat + (size_t)b*CIN*NPIX + pix0;

    if (t < NP) smem[11904 + t] = g_const[t];

    int lane = t & 31, w = t >> 5;
    int gid = lane >> 2, tig = lane & 3;
    int wm = (w & 7) * 16;
    int wn = (w >> 3) * 24;

    uint32_t s_as  = (uint32_t)__cvta_generic_to_shared(smem);
    uint32_t s_bhi = s_as + 6528*4;
    uint32_t s_blo = s_as + 9216*4;

    // per-thread load coords: A: 512 float4/stage -> 1 each; B: t<192 does hi+lo
    int a_kk = t >> 5;                 // 0..15
    int a_m0 = (t & 31) * 4;
    int b_kk = t / 12;
    int b_n0 = (t % 12) * 4;

#define LOAD_STAGE(s, k0)                                                            \
    do {                                                                             \
        CP_ASYNC16(s_as + ((s)*2176 + a_kk*AS_STRIDE + a_m0)*4,                      \
                   aBase + (size_t)((k0)+a_kk)*NPIX + a_m0);                         \
        if (t < 192) {                                                               \
            CP_ASYNC16(s_bhi + ((s)*896 + b_kk*BS_STRIDE + b_n0)*4,                  \
                       &g_Wf_hi[((k0)+b_kk)*NP + b_n0]);                             \
            CP_ASYNC16(s_blo + ((s)*896 + b_kk*BS_STRIDE + b_n0)*4,                  \
                       &g_Wf_lo[((k0)+b_kk)*NP + b_n0]);                             \
        }                                                                            \
        CP_COMMIT();                                                                 \
    } while (0)

    LOAD_STAGE(0, 0);
    LOAD_STAGE(1, BK);

    float d[3][4];
    #pragma unroll
    for (int nt = 0; nt < 3; ++nt)
        #pragma unroll
        for (int i = 0; i < 4; ++i) d[nt][i] = 0.f;

    for (int kc = 0; kc < NKCH; ++kc) {
        if (kc + 2 < NKCH) {
            LOAD_STAGE((kc+2)%3, (kc+2)*BK);
            asm volatile("cp.async.wait_group 2;\n");
        } else {
            asm volatile("cp.async.wait_group 0;\n");
        }
        __syncthreads();

        int s = kc % 3;
        const float*    As_ = smem + s*2176;
        const uint32_t* Bh  = (const uint32_t*)(smem + 6528) + s*896;
        const uint32_t* Bl  = (const uint32_t*)(smem + 9216) + s*896;

        #pragma unroll
        for (int ks = 0; ks < 2; ++ks) {
            int kb = ks*8;
            float a0 = As_[(kb+tig  )*AS_STRIDE + wm + gid];
            float a1 = As_[(kb+tig  )*AS_STRIDE + wm + gid + 8];
            float a2 = As_[(kb+tig+4)*AS_STRIDE + wm + gid];
            float a3 = As_[(kb+tig+4)*AS_STRIDE + wm + gid + 8];
            uint32_t ah[4], al[4];
            ah[0] = f2tf32(a0); al[0] = f2tf32(a0 - __uint_as_float(ah[0]));
            ah[1] = f2tf32(a1); al[1] = f2tf32(a1 - __uint_as_float(ah[1]));
            ah[2] = f2tf32(a2); al[2] = f2tf32(a2 - __uint_as_float(ah[2]));
            ah[3] = f2tf32(a3); al[3] = f2tf32(a3 - __uint_as_float(ah[3]));
            #pragma unroll
            for (int nt = 0; nt < 3; ++nt) {
                int n = wn + nt*8 + gid;
                uint32_t bh0 = Bh[(kb+tig  )*BS_STRIDE + n];
                uint32_t bh1 = Bh[(kb+tig+4)*BS_STRIDE + n];
                uint32_t bl0 = Bl[(kb+tig  )*BS_STRIDE + n];
                uint32_t bl1 = Bl[(kb+tig+4)*BS_STRIDE + n];
                mma_tf32(d[nt], ah, bh0, bh1);
                mma_tf32(d[nt], ah, bl0, bl1);
                mma_tf32(d[nt], al, bh0, bh1);
            }
        }
        __syncthreads();
    }

    // stage C into smem, then coalesced biased write-out
    float* Cs = smem;
    #pragma unroll
    for (int nt = 0; nt < 3; ++nt) {
        int col = wn + nt*8 + tig*2;
        Cs[(wm + gid    )*NP + col    ] = d[nt][0];
        Cs[(wm + gid    )*NP + col + 1] = d[nt][1];
        Cs[(wm + gid + 8)*NP + col    ] = d[nt][2];
        Cs[(wm + gid + 8)*NP + col + 1] = d[nt][3];
    }
    __syncthreads();
    const float4* csts4 = (const float4*)(smem + 11904);
    float4* outBase = (float4*)(g_pk + (size_t)m0*NP);
    #pragma unroll
    for (int it = 0; it < 3; ++it) {
        int i = t + 512*it;                // 1536 float4
        float4 v = ((const float4*)Cs)[i];
        float4 c = csts4[i % 12];
        v.x += c.x; v.y += c.y; v.z += c.z; v.w += c.w;
        outBase[i] = v;
    }
}

// ================= route: dedupe + softmax routing, one block per (b, instance) =================
__global__ __launch_bounds__(256) void route_kernel(
    const int* __restrict__ pts,
    const float* __restrict__ Wv,       // [258,16] (rel rows 256,257)
    const float* __restrict__ Wl,
    const float* __restrict__ bl,
    float* __restrict__ out)
{
    __shared__ unsigned bitmap[NPIX/32];
    __shared__ int counts[NPIX/32];
    __shared__ int offs[NPIX/32 + 1];
    __shared__ unsigned short cells[NPTS];
    __shared__ int sumY, sumX;
    __shared__ float scores[NCAPS][NPTS];
    __shared__ float vmatS[DV][NPTS];
    __shared__ float qwy[NCAPS], qwx[NCAPS];
    __shared__ float relVy[DV], relVx[DV], Wls[DV];

    int t  = threadIdx.x;
    int bi = blockIdx.x;
    const int* pbase = pts + (size_t)bi*2*NPTS;

    if (t < NPIX/32) bitmap[t] = 0u;
    if (t < NCAPS) { qwy[t] = g_QW[t*258 + 256]; qwx[t] = g_QW[t*258 + 257]; }
    if (t < DV) { relVy[t] = Wv[256*DV + t]; relVx[t] = Wv[257*DV + t]; Wls[t] = Wl[t]; }
    if (t == 0) { sumY = 0; sumX = 0; }
    __syncthreads();

    {
        int y = pbase[t] >> 4;
        int x = pbase[NPTS + t] >> 4;
        int key = y*WFD + x;
        atomicOr(&bitmap[key >> 5], 1u << (key & 31));
    }
    __syncthreads();
    if (t < NPIX/32) counts[t] = __popc(bitmap[t]);
    __syncthreads();
    if (t < 32) {
        int c0 = counts[t*4], c1 = counts[t*4+1], c2 = counts[t*4+2], c3 = counts[t*4+3];
        int s = c0 + c1 + c2 + c3;
        int run = s;
        #pragma unroll
        for (int off = 1; off < 32; off <<= 1) {
            int v = __shfl_up_sync(0xffffffffu, run, off);
            if (t >= off) run += v;
        }
        int excl = run - s;
        offs[t*4]   = excl;
        offs[t*4+1] = excl + c0;
        offs[t*4+2] = excl + c0 + c1;
        offs[t*4+3] = excl + c0 + c1 + c2;
        if (t == 31) offs[128] = run;
    }
    __syncthreads();
    if (t < NPIX/32) {
        unsigned bits = bitmap[t];
        int idx = offs[t];
        int sy = 0, sx = 0;
        while (bits) {
            int bpos = __ffs(bits) - 1;
            bits &= bits - 1;
            int cell = t*32 + bpos;
            cells[idx++] = (unsigned short)cell;
            sy += cell >> 6;
            sx += cell & 63;
        }
        if (counts[t]) { atomicAdd(&sumY, sy); atomicAdd(&sumX, sx); }
    }
    __syncthreads();

    int U = offs[NPIX/32];
    float nfl = (float)(U > 0 ? U : 1);
    float meanY = (float)sumY / nfl;
    float meanX = (float)sumX / nfl;

    if (t < U) {
        int cell = cells[t];
        const float4* pk4 = (const float4*)&g_pk[((size_t)(bi >> 5)*NPIX + cell)*NP];
        float4 q[9];
        #pragma unroll
        for (int i = 0; i < 9; ++i) q[i] = pk4[i];
        const float* pk = (const float*)q;

        float ry = ((float)(cell >> 6) - meanY) * (1.f/HFD);
        float rx = ((float)(cell & 63) - meanX) * (1.f/WFD);
        float act = 1.f/(1.f + expf(-pk[19]));
        float la  = logf(act + 1e-6f);
        #pragma unroll
        for (int c = 0; c < NCAPS; ++c)
            scores[c][t] = pk[c] + ry*qwy[c] + rx*qwx[c] + la;
        #pragma unroll
        for (int dd = 0; dd < DV; ++dd)
            vmatS[dd][t] = pk[20 + dd] + ry*relVy[dd] + rx*relVx[dd];
    }
    __syncthreads();

    int warp = t >> 5, lane = t & 31;
    for (int c = warp; c < NCAPS; c += 8) {
        float mx = -1e30f;
        for (int j = lane; j < U; j += 32) mx = fmaxf(mx, scores[c][j]);
        #pragma unroll
        for (int off = 16; off; off >>= 1) mx = fmaxf(mx, __shfl_xor_sync(0xffffffffu, mx, off));
        float se = 0.f;
        float acc[DV];
        #pragma unroll
        for (int dd = 0; dd < DV; ++dd) acc[dd] = 0.f;
        for (int j = lane; j < U; j += 32) {
            float e = expf(scores[c][j] - mx);
            se += e;
            #pragma unroll
            for (int dd = 0; dd < DV; ++dd) acc[dd] += e*vmatS[dd][j];
        }
        #pragma unroll
        for (int off = 16; off; off >>= 1) {
            se += __shfl_xor_sync(0xffffffffu, se, off);
            #pragma unroll
            for (int dd = 0; dd < DV; ++dd) acc[dd] += __shfl_xor_sync(0xffffffffu, acc[dd], off);
        }
        if (lane == 0) {
            float o = bl[0];
            float inv = 1.f/se;
            #pragma unroll
            for (int dd = 0; dd < DV; ++dd) o += (acc[dd]*inv)*Wls[dd];
            out[bi*NCAPS + c] = 1.f/(1.f + expf(-o));
        }
    }
}

extern "C" void kernel_launch(void* const* d_in, const int* in_sizes, int n_in,
                              void* d_out, int out_size) {
    const float* feat = (const float*)d_in[0];
    const float* Wp   = (const float*)d_in[1];
    const float* bp   = (const float*)d_in[2];
    const float* Wa   = (const float*)d_in[3];
    const float* ba   = (const float*)d_in[4];
    const float* Q    = (const float*)d_in[5];
    const float* Wk   = (const float*)d_in[6];
    const float* bk   = (const float*)d_in[7];
    const float* Wv   = (const float*)d_in[8];
    const float* bv   = (const float*)d_in[9];
    const float* Wl   = (const float*)d_in[10];
    const float* bl   = (const float*)d_in[11];
    const int*   pts  = (const int*)d_in[12];
    float* out = (float*)d_out;

    prep_kernel<<<1, 256>>>(Q, Wk, Wv, bp, ba, bk, bv);
    fold_kernel<<<CIN/64, 256>>>(Wp, Wa);
    gemm_kernel<<<(BATCH*NPIX)/BM, 512>>>(feat);
    route_kernel<<<BATCH*NINST, 256>>>(pts, Wv, Wl, bl, out);
}

// round 4
// speedup vs baseline: 1.0287x; 1.0287x over previous
#include <cuda_runtime.h>
#include <math.h>
#include <stdint.h>

#define HFD 64
#define WFD 64
#define CIN 1280
#define CCAP 256
#define NCAPS 19
#define DK 64
#define DV 16
#define NP 48              // 0..18 score-base, 19 act-logit, 20..35 V, 36..47 zero pad
#define BATCH 8
#define NINST 32
#define NPTS 256
#define NPIX (HFD*WFD)     // 4096

// ---- device scratch (no cudaMalloc allowed) ----
__device__ float    g_QW[NCAPS*258];          // 0.125 * Q @ Wk^T   [19,258]
__device__ float    g_W2[CCAP*NP];            // fold RHS [256 x 48]
__device__ uint32_t g_Wf_hi[CIN*NP];          // folded weights, tf32 hi
__device__ uint32_t g_Wf_lo[CIN*NP];          // tf32 lo residual
__device__ float    g_const[NP];
__device__ float    g_pk[BATCH*NPIX*NP];      // 6.3 MB

__device__ __forceinline__ uint32_t f2tf32(float x) {
    uint32_t r; asm("cvt.rna.tf32.f32 %0, %1;" : "=r"(r) : "f"(x)); return r;
}

// ================= prep: QW = 0.125*Q@Wk^T, W2 operand, folded biases (1 block) =================
__global__ __launch_bounds__(256) void prep_kernel(
    const float* __restrict__ Q,  const float* __restrict__ Wk,
    const float* __restrict__ Wv, const float* __restrict__ bp,
    const float* __restrict__ ba, const float* __restrict__ bk,
    const float* __restrict__ bv)
{
    int t = threadIdx.x;
    for (int idx = t; idx < NCAPS*258; idx += 256) {
        int c = idx / 258, j = idx % 258;
        float s = 0.f;
        #pragma unroll 8
        for (int o = 0; o < DK; ++o) s += Q[c*DK + o] * Wk[j*DK + o];
        g_QW[idx] = 0.125f * s;
    }
    __syncthreads();
    for (int idx = t; idx < CCAP*NP; idx += 256) {
        int j = idx / NP, col = idx % NP;
        float v = 0.f;
        if (col < NCAPS) v = g_QW[col*258 + j];
        else if (col >= 20 && col < 20 + DV) v = Wv[j*DV + (col - 20)];
        g_W2[idx] = v;
    }
    if (t < NP) {
        float s = 0.f;
        if (t < NCAPS) {
            for (int j = 0; j < CCAP; ++j) s += bp[j] * g_QW[t*258 + j];
            float qb = 0.f;
            for (int o = 0; o < DK; ++o) qb += Q[t*DK + o] * bk[o];
            s += 0.125f * qb;
        } else if (t == NCAPS) {
            s = ba[0];
        } else if (t < 20 + DV) {
            int o = t - 20;
            s = bv[o];
            for (int j = 0; j < CCAP; ++j) s += bp[j] * Wv[j*DV + o];
        }
        g_const[t] = s;
    }
}

// ================= fold: Wf[1280 x 48] = Wp^T @ W2, tf32-split =================
__global__ __launch_bounds__(256) void fold_kernel(const float* __restrict__ Wp,
                                                   const float* __restrict__ Wa) {
    __shared__ float wpS[64*64];
    __shared__ float w2S[64*NP];
    int t = threadIdx.x;
    int c0 = blockIdx.x * 64;
    int cl = t & 63;
    int tq = t >> 6;
    float acc[12];
    #pragma unroll
    for (int r = 0; r < 12; ++r) acc[r] = 0.f;

    for (int j0 = 0; j0 < CCAP; j0 += 64) {
        #pragma unroll
        for (int r = 0; r < 4; ++r) {
            int i = t + 256*r;
            int jj = i >> 4, c4 = (i & 15) * 4;
            *(float4*)&wpS[jj*64 + c4] = *(const float4*)&Wp[(size_t)(j0+jj)*CIN + c0 + c4];
        }
        #pragma unroll
        for (int r = 0; r < 3; ++r) {
            int i = t + 256*r;
            int jj = i / 12, c4 = (i % 12) * 4;
            *(float4*)&w2S[jj*NP + c4] = *(const float4*)&g_W2[(j0+jj)*NP + c4];
        }
        __syncthreads();
        #pragma unroll 4
        for (int jj = 0; jj < 64; ++jj) {
            float a = wpS[jj*64 + cl];
            #pragma unroll
            for (int r = 0; r < 12; ++r)
                acc[r] += a * w2S[jj*NP + tq*12 + r];
        }
        __syncthreads();
    }
    int c = c0 + cl;
    #pragma unroll
    for (int r = 0; r < 12; ++r) {
        int col = tq*12 + r;
        float s = (col == NCAPS) ? Wa[c] : acc[r];
        uint32_t hi = f2tf32(s);
        float lo = s - __uint_as_float(hi);
        g_Wf_hi[c*NP + col] = hi;
        g_Wf_lo[c*NP + col] = f2tf32(lo);
    }
}

// ================= GEMM: pk[32768 x 48] = feat @ Wfold, 3xTF32 mma, 3-stage cp.async =================
// 256 threads, 8 warps; each warp: 16 rows x 48 cols (6 n-tiles). No forced min-blocks.
#define BM 128
#define BK 16
#define AS_STRIDE 136
#define BS_STRIDE 56
#define NKCH (CIN/BK)      // 80

#define CP_ASYNC16(dst_s32, src) \
    asm volatile("cp.async.cg.shared.global [%0], [%1], 16;\n" :: "r"(dst_s32), "l"(src))
#define CP_COMMIT() asm volatile("cp.async.commit_group;\n")

__device__ __forceinline__ void mma_tf32(float* d, const uint32_t* a, uint32_t b0, uint32_t b1) {
    asm volatile(
        "mma.sync.aligned.m16n8k8.row.col.f32.tf32.tf32.f32 "
        "{%0,%1,%2,%3},{%4,%5,%6,%7},{%8,%9},{%0,%1,%2,%3};\n"
        : "+f"(d[0]), "+f"(d[1]), "+f"(d[2]), "+f"(d[3])
        : "r"(a[0]), "r"(a[1]), "r"(a[2]), "r"(a[3]), "r"(b0), "r"(b1));
}

// smem floats: As 3x2176=6528 | Bhi 3x896 @6528 | Blo 3x896 @9216 | csts 48 @11904
// epilogue: Cs 128x48=6144 reuses [0,6144)
__global__ __launch_bounds__(256) void gemm_kernel(const float* __restrict__ feat) {
    __shared__ __align__(16) float smem[11952];
    int t = threadIdx.x;
    int m0 = blockIdx.x * BM;
    int b  = m0 / NPIX;
    int pix0 = m0 % NPIX;
    const float* aBase = feat + (size_t)b*CIN*NPIX + pix0;

    if (t < NP) smem[11904 + t] = g_const[t];

    int lane = t & 31, w = t >> 5;
    int gid = lane >> 2, tig = lane & 3;
    int wm = w * 16;

    uint32_t s_as  = (uint32_t)__cvta_generic_to_shared(smem);
    uint32_t s_bhi = s_as + 6528*4;
    uint32_t s_blo = s_as + 9216*4;

    int a_kk0 = t >> 5;              // 0..7 (two loads: +0, +8)
    int a_m0  = (t & 31) * 4;
    int b_kk  = t / 12;
    int b_n0  = (t % 12) * 4;

#define LOAD_STAGE(s, k0)                                                            \
    do {                                                                             \
        CP_ASYNC16(s_as + ((s)*2176 + a_kk0*AS_STRIDE + a_m0)*4,                     \
                   aBase + (size_t)((k0)+a_kk0)*NPIX + a_m0);                        \
        CP_ASYNC16(s_as + ((s)*2176 + (a_kk0+8)*AS_STRIDE + a_m0)*4,                 \
                   aBase + (size_t)((k0)+a_kk0+8)*NPIX + a_m0);                      \
        if (t < 192) {                                                               \
            CP_ASYNC16(s_bhi + ((s)*896 + b_kk*BS_STRIDE + b_n0)*4,                  \
                       &g_Wf_hi[((k0)+b_kk)*NP + b_n0]);                             \
            CP_ASYNC16(s_blo + ((s)*896 + b_kk*BS_STRIDE + b_n0)*4,                  \
                       &g_Wf_lo[((k0)+b_kk)*NP + b_n0]);                             \
        }                                                                            \
        CP_COMMIT();                                                                 \
    } while (0)

    LOAD_STAGE(0, 0);
    LOAD_STAGE(1, BK);

    float d[6][4];
    #pragma unroll
    for (int nt = 0; nt < 6; ++nt)
        #pragma unroll
        for (int i = 0; i < 4; ++i) d[nt][i] = 0.f;

    for (int kc = 0; kc < NKCH; ++kc) {
        if (kc + 2 < NKCH) {
            LOAD_STAGE((kc+2)%3, (kc+2)*BK);
            asm volatile("cp.async.wait_group 2;\n");
        } else {
            asm volatile("cp.async.wait_group 0;\n");
        }
        __syncthreads();

        int s = kc % 3;
        const float*    As_ = smem + s*2176;
        const uint32_t* Bh  = (const uint32_t*)(smem + 6528) + s*896;
        const uint32_t* Bl  = (const uint32_t*)(smem + 9216) + s*896;

        #pragma unroll
        for (int ks = 0; ks < 2; ++ks) {
            int kb = ks*8;
            float a0 = As_[(kb+tig  )*AS_STRIDE + wm + gid];
            float a1 = As_[(kb+tig  )*AS_STRIDE + wm + gid + 8];
            float a2 = As_[(kb+tig+4)*AS_STRIDE + wm + gid];
            float a3 = As_[(kb+tig+4)*AS_STRIDE + wm + gid + 8];
            uint32_t ah[4], al[4];
            ah[0] = f2tf32(a0); al[0] = f2tf32(a0 - __uint_as_float(ah[0]));
            ah[1] = f2tf32(a1); al[1] = f2tf32(a1 - __uint_as_float(ah[1]));
            ah[2] = f2tf32(a2); al[2] = f2tf32(a2 - __uint_as_float(ah[2]));
            ah[3] = f2tf32(a3); al[3] = f2tf32(a3 - __uint_as_float(ah[3]));
            #pragma unroll
            for (int nt = 0; nt < 6; ++nt) {
                int n = nt*8 + gid;
                uint32_t bh0 = Bh[(kb+tig  )*BS_STRIDE + n];
                uint32_t bh1 = Bh[(kb+tig+4)*BS_STRIDE + n];
                uint32_t bl0 = Bl[(kb+tig  )*BS_STRIDE + n];
                uint32_t bl1 = Bl[(kb+tig+4)*BS_STRIDE + n];
                mma_tf32(d[nt], ah, bh0, bh1);
                mma_tf32(d[nt], ah, bl0, bl1);
                mma_tf32(d[nt], al, bh0, bh1);
            }
        }
        __syncthreads();
    }

    // stage C into smem, then coalesced biased write-out
    float* Cs = smem;
    #pragma unroll
    for (int nt = 0; nt < 6; ++nt) {
        int col = nt*8 + tig*2;
        Cs[(wm + gid    )*NP + col    ] = d[nt][0];
        Cs[(wm + gid    )*NP + col + 1] = d[nt][1];
        Cs[(wm + gid + 8)*NP + col    ] = d[nt][2];
        Cs[(wm + gid + 8)*NP + col + 1] = d[nt][3];
    }
    __syncthreads();
    const float4* csts4 = (const float4*)(smem + 11904);
    float4* outBase = (float4*)(g_pk + (size_t)m0*NP);
    #pragma unroll
    for (int it = 0; it < 6; ++it) {
        int i = t + 256*it;              // 1536 float4
        float4 v = ((const float4*)Cs)[i];
        float4 c = csts4[i % 12];
        v.x += c.x; v.y += c.y; v.z += c.z; v.w += c.w;
        outBase[i] = v;
    }
}

// ================= route: dedupe + softmax routing, one block per (b, instance) =================
__global__ __launch_bounds__(256) void route_kernel(
    const int* __restrict__ pts,
    const float* __restrict__ Wv,       // [258,16] (rel rows 256,257)
    const float* __restrict__ Wl,
    const float* __restrict__ bl,
    float* __restrict__ out)
{
    __shared__ unsigned bitmap[NPIX/32];
    __shared__ int counts[NPIX/32];
    __shared__ int offs[NPIX/32 + 1];
    __shared__ unsigned short cells[NPTS];
    __shared__ int sumY, sumX;
    __shared__ float scores[NCAPS][NPTS];
    __shared__ float vmatS[DV][NPTS];
    __shared__ float qwy[NCAPS], qwx[NCAPS];
    __shared__ float relVy[DV], relVx[DV], Wls[DV];

    int t  = threadIdx.x;
    int bi = blockIdx.x;
    const int* pbase = pts + (size_t)bi*2*NPTS;

    if (t < NPIX/32) bitmap[t] = 0u;
    if (t < NCAPS) { qwy[t] = g_QW[t*258 + 256]; qwx[t] = g_QW[t*258 + 257]; }
    if (t < DV) { relVy[t] = Wv[256*DV + t]; relVx[t] = Wv[257*DV + t]; Wls[t] = Wl[t]; }
    if (t == 0) { sumY = 0; sumX = 0; }
    __syncthreads();

    {
        int y = pbase[t] >> 4;
        int x = pbase[NPTS + t] >> 4;
        int key = y*WFD + x;
        atomicOr(&bitmap[key >> 5], 1u << (key & 31));
    }
    __syncthreads();
    if (t < NPIX/32) counts[t] = __popc(bitmap[t]);
    __syncthreads();
    if (t < 32) {
        int c0 = counts[t*4], c1 = counts[t*4+1], c2 = counts[t*4+2], c3 = counts[t*4+3];
        int s = c0 + c1 + c2 + c3;
        int run = s;
        #pragma unroll
        for (int off = 1; off < 32; off <<= 1) {
            int v = __shfl_up_sync(0xffffffffu, run, off);
            if (t >= off) run += v;
        }
        int excl = run - s;
        offs[t*4]   = excl;
        offs[t*4+1] = excl + c0;
        offs[t*4+2] = excl + c0 + c1;
        offs[t*4+3] = excl + c0 + c1 + c2;
        if (t == 31) offs[128] = run;
    }
    __syncthreads();
    if (t < NPIX/32) {
        unsigned bits = bitmap[t];
        int idx = offs[t];
        int sy = 0, sx = 0;
        while (bits) {
            int bpos = __ffs(bits) - 1;
            bits &= bits - 1;
            int cell = t*32 + bpos;
            cells[idx++] = (unsigned short)cell;
            sy += cell >> 6;
            sx += cell & 63;
        }
        if (counts[t]) { atomicAdd(&sumY, sy); atomicAdd(&sumX, sx); }
    }
    __syncthreads();

    int U = offs[NPIX/32];
    float nfl = (float)(U > 0 ? U : 1);
    float meanY = (float)sumY / nfl;
    float meanX = (float)sumX / nfl;

    if (t < U) {
        int cell = cells[t];
        const float4* pk4 = (const float4*)&g_pk[((size_t)(bi >> 5)*NPIX + cell)*NP];
        float4 q[9];
        #pragma unroll
        for (int i = 0; i < 9; ++i) q[i] = pk4[i];
        const float* pk = (const float*)q;

        float ry = ((float)(cell >> 6) - meanY) * (1.f/HFD);
        float rx = ((float)(cell & 63) - meanX) * (1.f/WFD);
        float act = 1.f/(1.f + expf(-pk[19]));
        float la  = logf(act + 1e-6f);
        #pragma unroll
        for (int c = 0; c < NCAPS; ++c)
            scores[c][t] = pk[c] + ry*qwy[c] + rx*qwx[c] + la;
        #pragma unroll
        for (int dd = 0; dd < DV; ++dd)
            vmatS[dd][t] = pk[20 + dd] + ry*relVy[dd] + rx*relVx[dd];
    }
    __syncthreads();

    int warp = t >> 5, lane = t & 31;
    for (int c = warp; c < NCAPS; c += 8) {
        float mx = -1e30f;
        for (int j = lane; j < U; j += 32) mx = fmaxf(mx, scores[c][j]);
        #pragma unroll
        for (int off = 16; off; off >>= 1) mx = fmaxf(mx, __shfl_xor_sync(0xffffffffu, mx, off));
        float se = 0.f;
        float acc[DV];
        #pragma unroll
        for (int dd = 0; dd < DV; ++dd) acc[dd] = 0.f;
        for (int j = lane; j < U; j += 32) {
            float e = expf(scores[c][j] - mx);
            se += e;
            #pragma unroll
            for (int dd = 0; dd < DV; ++dd) acc[dd] += e*vmatS[dd][j];
        }
        #pragma unroll
        for (int off = 16; off; off >>= 1) {
            se += __shfl_xor_sync(0xffffffffu, se, off);
            #pragma unroll
            for (int dd = 0; dd < DV; ++dd) acc[dd] += __shfl_xor_sync(0xffffffffu, acc[dd], off);
        }
        if (lane == 0) {
            float o = bl[0];
            float inv = 1.f/se;
            #pragma unroll
            for (int dd = 0; dd < DV; ++dd) o += (acc[dd]*inv)*Wls[dd];
            out[bi*NCAPS + c] = 1.f/(1.f + expf(-o));
        }
    }
}

extern "C" void kernel_launch(void* const* d_in, const int* in_sizes, int n_in,
                              void* d_out, int out_size) {
    const float* feat = (const float*)d_in[0];
    const float* Wp   = (const float*)d_in[1];
    const float* bp   = (const float*)d_in[2];
    const float* Wa   = (const float*)d_in[3];
    const float* ba   = (const float*)d_in[4];
    const float* Q    = (const float*)d_in[5];
    const float* Wk   = (const float*)d_in[6];
    const float* bk   = (const float*)d_in[7];
    const float* Wv   = (const float*)d_in[8];
    const float* bv   = (const float*)d_in[9];
    const float* Wl   = (const float*)d_in[10];
    const float* bl   = (const float*)d_in[11];
    const int*   pts  = (const int*)d_in[12];
    float* out = (float*)d_out;

    prep_kernel<<<1, 256>>>(Q, Wk, Wv, bp, ba, bk, bv);
    fold_kernel<<<CIN/64, 256>>>(Wp, Wa);
    gemm_kernel<<<(BATCH*NPIX)/BM, 256>>>(feat);
    route_kernel<<<BATCH*NINST, 256>>>(pts, Wv, Wl, bl, out);
}

// round 5
// speedup vs baseline: 1.9482x; 1.8938x over previous
#include <cuda_runtime.h>
#include <math.h>
#include <stdint.h>

#define HFD 64
#define WFD 64
#define CIN 1280
#define CCAP 256
#define NCAPS 19
#define DK 64
#define DV 16
#define NP 48              // 0..18 score-base, 19 act-logit, 20..35 V, 36..47 zero pad
#define BATCH 8
#define NINST 32
#define NPTS 256
#define NPIX (HFD*WFD)     // 4096

// ---- device scratch (no cudaMalloc allowed) ----
__device__ float    g_QW[NCAPS*258];          // 0.125 * Q @ Wk^T   [19,258]
__device__ uint32_t g_Wf_hi[CIN*NP];          // folded weights, tf32 hi
__device__ uint32_t g_Wf_lo[CIN*NP];          // tf32 lo residual
__device__ float    g_const[NP];
__device__ float    g_pk[BATCH*NPIX*NP];      // 6.3 MB

__device__ __forceinline__ uint32_t f2tf32(float x) {
    uint32_t r; asm("cvt.rna.tf32.f32 %0, %1;" : "=r"(r) : "f"(x)); return r;
}

// ================= kernel A: QW = 0.125 * Q @ Wk^T  [19 x 258] =================
__global__ void qw_kernel(const float* __restrict__ Q, const float* __restrict__ Wk) {
    int idx = blockIdx.x * 256 + threadIdx.x;
    if (idx >= NCAPS*258) return;
    int c = idx / 258, j = idx % 258;
    float s = 0.f;
    #pragma unroll 8
    for (int o = 0; o < DK; ++o) s += Q[c*DK + o] * Wk[j*DK + o];
    g_QW[idx] = 0.125f * s;
}

// ================= kernel B: fold Wp into [QW-score | act | V] cols, tf32 split =================
__global__ void fold_kernel(const float* __restrict__ Wp, const float* __restrict__ Wa,
                            const float* __restrict__ Wv) {
    __shared__ float wp[CCAP];
    int c = blockIdx.x;
    int t = threadIdx.x;                 // 0..63
    for (int j = t; j < CCAP; j += 64) wp[j] = Wp[j*CIN + c];
    __syncthreads();
    if (t >= NP) return;
    float s = 0.f;
    if (t < NCAPS) {
        #pragma unroll 4
        for (int j = 0; j < CCAP; ++j) s += wp[j] * g_QW[t*258 + j];
    } else if (t == NCAPS) {
        s = Wa[c];
    } else if (t < 20 + DV) {
        int o = t - 20;
        #pragma unroll 4
        for (int j = 0; j < CCAP; ++j) s += wp[j] * Wv[j*DV + o];
    }
    uint32_t hi = f2tf32(s);
    float lo = s - __uint_as_float(hi);
    g_Wf_hi[c*NP + t] = hi;
    g_Wf_lo[c*NP + t] = f2tf32(lo);
}

// ================= kernel C: fold biases =================
__global__ void const_kernel(const float* __restrict__ bp, const float* __restrict__ ba,
                             const float* __restrict__ Q,  const float* __restrict__ bk,
                             const float* __restrict__ Wv, const float* __restrict__ bv) {
    int t = threadIdx.x;                 // 0..47
    float s = 0.f;
    if (t < NCAPS) {
        for (int j = 0; j < CCAP; ++j) s += bp[j] * g_QW[t*258 + j];
        float qb = 0.f;
        for (int o = 0; o < DK; ++o) qb += Q[t*DK + o] * bk[o];
        s += 0.125f * qb;
    } else if (t == NCAPS) {
        s = ba[0];
    } else if (t < 20 + DV) {
        int o = t - 20;
        s = bv[o];
        for (int j = 0; j < CCAP; ++j) s += bp[j] * Wv[j*DV + o];
    }
    g_const[t] = s;
}

// ================= kernel 1: GEMM  pk[32768 x 48] = feat[32768 x 1280] @ Wfold =================
// 3xTF32 mma.sync.m16n8k8, BM=128, BN=48, BK=16, 8 warps (each warp: 16 rows x 48 cols)
// EXACT R2 version (measured 90us): 2-stage cp.async ping-pong, smem 31.9KB.
#define BM 128
#define BK 16
#define AS_STRIDE 136
#define BS_STRIDE 56
#define NKCH (CIN/BK)      // 80

#define CP_ASYNC16(dst_s32, src) \
    asm volatile("cp.async.cg.shared.global [%0], [%1], 16;\n" :: "r"(dst_s32), "l"(src))
#define CP_COMMIT() asm volatile("cp.async.commit_group;\n")

__device__ __forceinline__ void mma_tf32(float* d, const uint32_t* a, uint32_t b0, uint32_t b1) {
    asm volatile(
        "mma.sync.aligned.m16n8k8.row.col.f32.tf32.tf32.f32 "
        "{%0,%1,%2,%3},{%4,%5,%6,%7},{%8,%9},{%0,%1,%2,%3};\n"
        : "+f"(d[0]), "+f"(d[1]), "+f"(d[2]), "+f"(d[3])
        : "r"(a[0]), "r"(a[1]), "r"(a[2]), "r"(a[3]), "r"(b0), "r"(b1));
}

// smem float layout (union):
//   As   : 2 bufs x 16 x 136  at [0, 4352)
//   Bhi  : 2 bufs x 16 x 56   at [4352, 6144)
//   Blo  : 2 bufs x 16 x 56   at [6144, 7936)
//   Cs   : 128 x 48           at [0, 6144)   (after mainloop)
//   csts : 48                 at [7936, 7984)
__global__ __launch_bounds__(256) void gemm_kernel(const float* __restrict__ feat) {
    __shared__ __align__(16) float smem[7984];
    int t = threadIdx.x;
    int m0 = blockIdx.x * BM;
    int b  = m0 / NPIX;
    int pix0 = m0 % NPIX;
    const float* aBase = feat + (size_t)b*CIN*NPIX + pix0;

    if (t < NP) smem[7936 + t] = g_const[t];

    int lane = t & 31, w = t >> 5;
    int gid = lane >> 2, tig = lane & 3;
    int wm = w * 16;

    uint32_t s_as  = (uint32_t)__cvta_generic_to_shared(smem);
    uint32_t s_bhi = s_as + 4352*4;
    uint32_t s_blo = s_as + 6144*4;

    // per-thread load coords
    int a_kk0 = t >> 5;              // first of two A float4 loads
    int a_m0  = (t & 31) * 4;
    int b_kk  = t / 12;              // B loads: t<192
    int b_n0  = (t % 12) * 4;

    // prologue: stage 0
    {
        int k0 = 0;
        #pragma unroll
        for (int it = 0; it < 2; ++it) {
            int kk = a_kk0 + it*8;
            CP_ASYNC16(s_as + (kk*AS_STRIDE + a_m0)*4,
                       aBase + (size_t)(k0+kk)*NPIX + a_m0);
        }
        if (t < 192) {
            CP_ASYNC16(s_bhi + (b_kk*BS_STRIDE + b_n0)*4, &g_Wf_hi[(k0+b_kk)*NP + b_n0]);
            CP_ASYNC16(s_blo + (b_kk*BS_STRIDE + b_n0)*4, &g_Wf_lo[(k0+b_kk)*NP + b_n0]);
        }
        CP_COMMIT();
    }

    float d[6][4];
    #pragma unroll
    for (int nt = 0; nt < 6; ++nt)
        #pragma unroll
        for (int i = 0; i < 4; ++i) d[nt][i] = 0.f;

    for (int kc = 0; kc < NKCH; ++kc) {
        if (kc + 1 < NKCH) {
            int k0 = (kc+1)*BK;
            int p = (kc+1) & 1;
            #pragma unroll
            for (int it = 0; it < 2; ++it) {
                int kk = a_kk0 + it*8;
                CP_ASYNC16(s_as + (p*2176 + kk*AS_STRIDE + a_m0)*4,
                           aBase + (size_t)(k0+kk)*NPIX + a_m0);
            }
            if (t < 192) {
                CP_ASYNC16(s_bhi + (p*896 + b_kk*BS_STRIDE + b_n0)*4, &g_Wf_hi[(k0+b_kk)*NP + b_n0]);
                CP_ASYNC16(s_blo + (p*896 + b_kk*BS_STRIDE + b_n0)*4, &g_Wf_lo[(k0+b_kk)*NP + b_n0]);
            }
            CP_COMMIT();
            asm volatile("cp.async.wait_group 1;\n");
        } else {
            asm volatile("cp.async.wait_group 0;\n");
        }
        __syncthreads();

        const float*    As_ = smem + (kc&1)*2176;
        const uint32_t* Bh  = (const uint32_t*)(smem + 4352) + (kc&1)*896;
        const uint32_t* Bl  = (const uint32_t*)(smem + 6144) + (kc&1)*896;

        #pragma unroll
        for (int ks = 0; ks < 2; ++ks) {
            int kb = ks*8;
            float a0 = As_[(kb+tig  )*AS_STRIDE + wm + gid];
            float a1 = As_[(kb+tig  )*AS_STRIDE + wm + gid + 8];
            float a2 = As_[(kb+tig+4)*AS_STRIDE + wm + gid];
            float a3 = As_[(kb+tig+4)*AS_STRIDE + wm + gid + 8];
            uint32_t ah[4], al[4];
            ah[0] = f2tf32(a0); al[0] = f2tf32(a0 - __uint_as_float(ah[0]));
            ah[1] = f2tf32(a1); al[1] = f2tf32(a1 - __uint_as_float(ah[1]));
            ah[2] = f2tf32(a2); al[2] = f2tf32(a2 - __uint_as_float(ah[2]));
            ah[3] = f2tf32(a3); al[3] = f2tf32(a3 - __uint_as_float(ah[3]));
            #pragma unroll
            for (int nt = 0; nt < 6; ++nt) {
                int n = nt*8 + gid;
                uint32_t bh0 = Bh[(kb+tig  )*BS_STRIDE + n];
                uint32_t bh1 = Bh[(kb+tig+4)*BS_STRIDE + n];
                uint32_t bl0 = Bl[(kb+tig  )*BS_STRIDE + n];
                uint32_t bl1 = Bl[(kb+tig+4)*BS_STRIDE + n];
                mma_tf32(d[nt], ah, bh0, bh1);
                mma_tf32(d[nt], ah, bl0, bl1);
                mma_tf32(d[nt], al, bh0, bh1);
            }
        }
        __syncthreads();
    }

    // stage C into smem, then coalesced write-out with bias add
    float* Cs = smem;
    #pragma unroll
    for (int nt = 0; nt < 6; ++nt) {
        int col = nt*8 + tig*2;
        Cs[(wm + gid    )*NP + col    ] = d[nt][0];
        Cs[(wm + gid    )*NP + col + 1] = d[nt][1];
        Cs[(wm + gid + 8)*NP + col    ] = d[nt][2];
        Cs[(wm + gid + 8)*NP + col + 1] = d[nt][3];
    }
    __syncthreads();
    const float4* csts4 = (const float4*)(smem + 7936);
    float4* outBase = (float4*)(g_pk + (size_t)m0*NP);
    #pragma unroll
    for (int it = 0; it < 6; ++it) {
        int i = t + 256*it;              // 1536 float4 total
        float4 v = ((const float4*)Cs)[i];
        float4 c = csts4[i % 12];
        v.x += c.x; v.y += c.y; v.z += c.z; v.w += c.w;
        outBase[i] = v;
    }
}

// ================= kernel 2: dedupe + routing (verified 16us version) =================
__global__ __launch_bounds__(256) void route_kernel(
    const int* __restrict__ pts,
    const float* __restrict__ Wv,       // [258,16] (rel rows 256,257)
    const float* __restrict__ Wl,
    const float* __restrict__ bl,
    float* __restrict__ out)
{
    __shared__ unsigned bitmap[NPIX/32];
    __shared__ int counts[NPIX/32];
    __shared__ int offs[NPIX/32 + 1];
    __shared__ unsigned short cells[NPTS];
    __shared__ int sumY, sumX;
    __shared__ float scores[NCAPS][NPTS];
    __shared__ float vmatS[DV][NPTS];
    __shared__ float qwy[NCAPS], qwx[NCAPS];
    __shared__ float relVy[DV], relVx[DV], Wls[DV];

    int t  = threadIdx.x;
    int bi = blockIdx.x;
    const int* pbase = pts + (size_t)bi*2*NPTS;

    if (t < NPIX/32) bitmap[t] = 0u;
    if (t < NCAPS) { qwy[t] = g_QW[t*258 + 256]; qwx[t] = g_QW[t*258 + 257]; }
    if (t < DV) { relVy[t] = Wv[256*DV + t]; relVx[t] = Wv[257*DV + t]; Wls[t] = Wl[t]; }
    if (t == 0) { sumY = 0; sumX = 0; }
    __syncthreads();

    {
        int y = pbase[t] >> 4;
        int x = pbase[NPTS + t] >> 4;
        int key = y*WFD + x;
        atomicOr(&bitmap[key >> 5], 1u << (key & 31));
    }
    __syncthreads();
    if (t < NPIX/32) counts[t] = __popc(bitmap[t]);
    __syncthreads();
    if (t < 32) {
        int c0 = counts[t*4], c1 = counts[t*4+1], c2 = counts[t*4+2], c3 = counts[t*4+3];
        int s = c0 + c1 + c2 + c3;
        int run = s;
        #pragma unroll
        for (int off = 1; off < 32; off <<= 1) {
            int v = __shfl_up_sync(0xffffffffu, run, off);
            if (t >= off) run += v;
        }
        int excl = run - s;
        offs[t*4]   = excl;
        offs[t*4+1] = excl + c0;
        offs[t*4+2] = excl + c0 + c1;
        offs[t*4+3] = excl + c0 + c1 + c2;
        if (t == 31) offs[128] = run;
    }
    __syncthreads();
    if (t < NPIX/32) {
        unsigned bits = bitmap[t];
        int idx = offs[t];
        int sy = 0, sx = 0;
        while (bits) {
            int bpos = __ffs(bits) - 1;
            bits &= bits - 1;
            int cell = t*32 + bpos;
            cells[idx++] = (unsigned short)cell;
            sy += cell >> 6;
            sx += cell & 63;
        }
        if (counts[t]) { atomicAdd(&sumY, sy); atomicAdd(&sumX, sx); }
    }
    __syncthreads();

    int U = offs[NPIX/32];
    float nfl = (float)(U > 0 ? U : 1);
    float meanY = (float)sumY / nfl;
    float meanX = (float)sumX / nfl;

    if (t < U) {
        int cell = cells[t];
        const float4* pk4 = (const float4*)&g_pk[((size_t)(bi >> 5)*NPIX + cell)*NP];
        float4 q[9];
        #pragma unroll
        for (int i = 0; i < 9; ++i) q[i] = pk4[i];
        const float* pk = (const float*)q;

        float ry = ((float)(cell >> 6) - meanY) * (1.f/HFD);
        float rx = ((float)(cell & 63) - meanX) * (1.f/WFD);
        float act = 1.f/(1.f + expf(-pk[19]));
        float la  = logf(act + 1e-6f);
        #pragma unroll
        for (int c = 0; c < NCAPS; ++c)
            scores[c][t] = pk[c] + ry*qwy[c] + rx*qwx[c] + la;
        #pragma unroll
        for (int dd = 0; dd < DV; ++dd)
            vmatS[dd][t] = pk[20 + dd] + ry*relVy[dd] + rx*relVx[dd];
    }
    __syncthreads();

    int warp = t >> 5, lane = t & 31;
    for (int c = warp; c < NCAPS; c += 8) {
        float mx = -1e30f;
        for (int j = lane; j < U; j += 32) mx = fmaxf(mx, scores[c][j]);
        #pragma unroll
        for (int off = 16; off; off >>= 1) mx = fmaxf(mx, __shfl_xor_sync(0xffffffffu, mx, off));
        float se = 0.f;
        float acc[DV];
        #pragma unroll
        for (int dd = 0; dd < DV; ++dd) acc[dd] = 0.f;
        for (int j = lane; j < U; j += 32) {
            float e = expf(scores[c][j] - mx);
            se += e;
            #pragma unroll
            for (int dd = 0; dd < DV; ++dd) acc[dd] += e*vmatS[dd][j];
        }
        #pragma unroll
        for (int off = 16; off; off >>= 1) {
            se += __shfl_xor_sync(0xffffffffu, se, off);
            #pragma unroll
            for (int dd = 0; dd < DV; ++dd) acc[dd] += __shfl_xor_sync(0xffffffffu, acc[dd], off);
        }
        if (lane == 0) {
            float o = bl[0];
            float inv = 1.f/se;
            #pragma unroll
            for (int dd = 0; dd < DV; ++dd) o += (acc[dd]*inv)*Wls[dd];
            out[bi*NCAPS + c] = 1.f/(1.f + expf(-o));
        }
    }
}

extern "C" void kernel_launch(void* const* d_in, const int* in_sizes, int n_in,
                              void* d_out, int out_size) {
    const float* feat = (const float*)d_in[0];
    const float* Wp   = (const float*)d_in[1];
    const float* bp   = (const float*)d_in[2];
    const float* Wa   = (const float*)d_in[3];
    const float* ba   = (const float*)d_in[4];
    const float* Q    = (const float*)d_in[5];
    const float* Wk   = (const float*)d_in[6];
    const float* bk   = (const float*)d_in[7];
    const float* Wv   = (const float*)d_in[8];
    const float* bv   = (const float*)d_in[9];
    const float* Wl   = (const float*)d_in[10];
    const float* bl   = (const float*)d_in[11];
    const int*   pts  = (const int*)d_in[12];
    float* out = (float*)d_out;

    qw_kernel<<<(NCAPS*258 + 255)/256, 256>>>(Q, Wk);
    fold_kernel<<<CIN, 64>>>(Wp, Wa, Wv);
    const_kernel<<<1, NP>>>(bp, ba, Q, bk, Wv, bv);
    gemm_kernel<<<(BATCH*NPIX)/BM, 256>>>(feat);
    route_kernel<<<BATCH*NINST, 256>>>(pts, Wv, Wl, bl, out);
}

// round 6
// speedup vs baseline: 2.3354x; 1.1988x over previous
#include <cuda_runtime.h>
#include <cuda_bf16.h>
#include <math.h>
#include <stdint.h>

#define HFD 64
#define WFD 64
#define CIN 1280
#define CCAP 256
#define NCAPS 19
#define DK 64
#define DV 16
#define NP 48              // 0..18 score-base, 19 act-logit, 20..35 V, 36..47 zero pad
#define BATCH 8
#define NINST 32
#define NPTS 256
#define NPIX (HFD*WFD)     // 4096

// ---- device scratch (no cudaMalloc allowed) ----
__device__ float    g_QW[NCAPS*258];          // 0.125 * Q @ Wk^T   [19,258]
__device__ uint32_t g_Wbh[(CIN/2)*NP];        // folded weights, bf16 hi, packed k-pairs
__device__ uint32_t g_Wbl[(CIN/2)*NP];        // bf16 lo residual, packed k-pairs
__device__ float    g_const[NP];
__device__ float    g_pk[BATCH*NPIX*NP];      // 6.3 MB

__device__ __forceinline__ uint32_t packbf2(float x, float y) {
    __nv_bfloat162 h = __floats2bfloat162_rn(x, y);   // .x = x (low half)
    return *(uint32_t*)&h;
}

// ================= kernel A: QW = 0.125 * Q @ Wk^T  [19 x 258] =================
__global__ void qw_kernel(const float* __restrict__ Q, const float* __restrict__ Wk) {
    int idx = blockIdx.x * 256 + threadIdx.x;
    if (idx >= NCAPS*258) return;
    int c = idx / 258, j = idx % 258;
    float s = 0.f;
    #pragma unroll 8
    for (int o = 0; o < DK; ++o) s += Q[c*DK + o] * Wk[j*DK + o];
    g_QW[idx] = 0.125f * s;
}

// ================= kernel B: fold Wp -> bf16 hi/lo packed pairs (2 channels/block) =========
__global__ void fold_kernel(const float* __restrict__ Wp, const float* __restrict__ Wa,
                            const float* __restrict__ Wv) {
    __shared__ float wp[2*CCAP];
    int c2 = blockIdx.x;             // 0..639
    int c0 = c2 * 2;
    int t = threadIdx.x;             // 0..95
    for (int i = t; i < 2*CCAP; i += 96) {
        int j = i >> 1, which = i & 1;
        wp[which*CCAP + j] = Wp[(size_t)j*CIN + c0 + which];
    }
    __syncthreads();
    if (t >= NP) return;
    float s0 = 0.f, s1 = 0.f;
    if (t < NCAPS) {
        #pragma unroll 4
        for (int j = 0; j < CCAP; ++j) {
            float q = g_QW[t*258 + j];
            s0 += wp[j] * q;
            s1 += wp[CCAP + j] * q;
        }
    } else if (t == NCAPS) {
        s0 = Wa[c0]; s1 = Wa[c0 + 1];
    } else if (t < 20 + DV) {
        int o = t - 20;
        #pragma unroll 4
        for (int j = 0; j < CCAP; ++j) {
            float v = Wv[j*DV + o];
            s0 += wp[j] * v;
            s1 += wp[CCAP + j] * v;
        }
    }
    __nv_bfloat16 h0 = __float2bfloat16_rn(s0);
    __nv_bfloat16 h1 = __float2bfloat16_rn(s1);
    float l0 = s0 - __bfloat162float(h0);
    float l1 = s1 - __bfloat162float(h1);
    uint32_t hi; { __nv_bfloat162 p{h0, h1}; hi = *(uint32_t*)&p; }
    g_Wbh[c2*NP + t] = hi;
    g_Wbl[c2*NP + t] = packbf2(l0, l1);
}

// ================= kernel C: fold biases =================
__global__ void const_kernel(const float* __restrict__ bp, const float* __restrict__ ba,
                             const float* __restrict__ Q,  const float* __restrict__ bk,
                             const float* __restrict__ Wv, const float* __restrict__ bv) {
    int t = threadIdx.x;                 // 0..47
    float s = 0.f;
    if (t < NCAPS) {
        for (int j = 0; j < CCAP; ++j) s += bp[j] * g_QW[t*258 + j];
        float qb = 0.f;
        for (int o = 0; o < DK; ++o) qb += Q[t*DK + o] * bk[o];
        s += 0.125f * qb;
    } else if (t == NCAPS) {
        s = ba[0];
    } else if (t < 20 + DV) {
        int o = t - 20;
        s = bv[o];
        for (int j = 0; j < CCAP; ++j) s += bp[j] * Wv[j*DV + o];
    }
    g_const[t] = s;
}

// ================= kernel 1: GEMM  pk[32768 x 48] = feat @ Wfold, 3xBF16 mma =================
// BM=64, 128 threads (4 warps, each 16 rows x 48 cols), 2-stage cp.async, grid 512.
#define BM 64
#define BK 16
#define AS_STRIDE 68
#define BS_STRIDE 56
#define NKCH (CIN/BK)      // 80

#define CP_ASYNC16(dst_s32, src) \
    asm volatile("cp.async.cg.shared.global [%0], [%1], 16;\n" :: "r"(dst_s32), "l"(src))
#define CP_COMMIT() asm volatile("cp.async.commit_group;\n")

__device__ __forceinline__ void mma_bf16(float* d, const uint32_t* a, uint32_t b0, uint32_t b1) {
    asm volatile(
        "mma.sync.aligned.m16n8k16.row.col.f32.bf16.bf16.f32 "
        "{%0,%1,%2,%3},{%4,%5,%6,%7},{%8,%9},{%0,%1,%2,%3};\n"
        : "+f"(d[0]), "+f"(d[1]), "+f"(d[2]), "+f"(d[3])
        : "r"(a[0]), "r"(a[1]), "r"(a[2]), "r"(a[3]), "r"(b0), "r"(b1));
}

// smem floats: As 2x(16x68)=2176 | Bh 2x448 @2176 | Bl 2x448 @3072 | csts 48 @3968
// epilogue: Cs 64x48=3072 reuses [0,3072)
__global__ __launch_bounds__(128) void gemm_kernel(const float* __restrict__ feat) {
    __shared__ __align__(16) float smem[4016];
    int t = threadIdx.x;
    int m0 = blockIdx.x * BM;
    int b  = m0 / NPIX;
    int pix0 = m0 % NPIX;
    const float* aBase = feat + (size_t)b*CIN*NPIX + pix0;

    if (t < NP) smem[3968 + t] = g_const[t];

    int lane = t & 31, w = t >> 5;
    int gid = lane >> 2, tig = lane & 3;
    int wm = w * 16;

    uint32_t s_as = (uint32_t)__cvta_generic_to_shared(smem);
    uint32_t s_bh = s_as + 2176*4;
    uint32_t s_bl = s_as + 3072*4;

    // A: 256 float4/stage over 128 threads -> 2 each
    int a_kk0 = t >> 4;              // 0..7 (second: +8)
    int a_m0  = (t & 15) * 4;
    // B: t<96: hi + lo 16B each
    int b_kp  = t / 12;              // 0..7
    int b_n0  = (t % 12) * 4;

#define LOAD_STAGE(p, k0)                                                            \
    do {                                                                             \
        CP_ASYNC16(s_as + ((p)*1088 + a_kk0*AS_STRIDE + a_m0)*4,                     \
                   aBase + (size_t)((k0)+a_kk0)*NPIX + a_m0);                        \
        CP_ASYNC16(s_as + ((p)*1088 + (a_kk0+8)*AS_STRIDE + a_m0)*4,                 \
                   aBase + (size_t)((k0)+a_kk0+8)*NPIX + a_m0);                      \
        if (t < 96) {                                                                \
            CP_ASYNC16(s_bh + ((p)*448 + b_kp*BS_STRIDE + b_n0)*4,                   \
                       &g_Wbh[((k0)/2 + b_kp)*NP + b_n0]);                           \
            CP_ASYNC16(s_bl + ((p)*448 + b_kp*BS_STRIDE + b_n0)*4,                   \
                       &g_Wbl[((k0)/2 + b_kp)*NP + b_n0]);                           \
        }                                                                            \
        CP_COMMIT();                                                                 \
    } while (0)

    LOAD_STAGE(0, 0);

    float d[6][4];
    #pragma unroll
    for (int nt = 0; nt < 6; ++nt)
        #pragma unroll
        for (int i = 0; i < 4; ++i) d[nt][i] = 0.f;

    for (int kc = 0; kc < NKCH; ++kc) {
        if (kc + 1 < NKCH) {
            LOAD_STAGE((kc+1) & 1, (kc+1)*BK);
            asm volatile("cp.async.wait_group 1;\n");
        } else {
            asm volatile("cp.async.wait_group 0;\n");
        }
        __syncthreads();

        const float*    As_ = smem + (kc&1)*1088;
        const uint32_t* Bh  = (const uint32_t*)(smem + 2176) + (kc&1)*448;
        const uint32_t* Bl  = (const uint32_t*)(smem + 3072) + (kc&1)*448;

        int m = wm + gid;
        float L00 = As_[(2*tig  )*AS_STRIDE + m];
        float L01 = As_[(2*tig+1)*AS_STRIDE + m];
        float L08 = As_[(2*tig+8)*AS_STRIDE + m];
        float L09 = As_[(2*tig+9)*AS_STRIDE + m];
        float M00 = As_[(2*tig  )*AS_STRIDE + m + 8];
        float M01 = As_[(2*tig+1)*AS_STRIDE + m + 8];
        float M08 = As_[(2*tig+8)*AS_STRIDE + m + 8];
        float M09 = As_[(2*tig+9)*AS_STRIDE + m + 8];

        uint32_t ah[4], al[4];
        {
            __nv_bfloat162 h;
            h = __floats2bfloat162_rn(L00, L01); ah[0] = *(uint32_t*)&h;
            al[0] = packbf2(L00 - __bfloat162float(h.x), L01 - __bfloat162float(h.y));
            h = __floats2bfloat162_rn(M00, M01); ah[1] = *(uint32_t*)&h;
            al[1] = packbf2(M00 - __bfloat162float(h.x), M01 - __bfloat162float(h.y));
            h = __floats2bfloat162_rn(L08, L09); ah[2] = *(uint32_t*)&h;
            al[2] = packbf2(L08 - __bfloat162float(h.x), L09 - __bfloat162float(h.y));
            h = __floats2bfloat162_rn(M08, M09); ah[3] = *(uint32_t*)&h;
            al[3] = packbf2(M08 - __bfloat162float(h.x), M09 - __bfloat162float(h.y));
        }

        #pragma unroll
        for (int nt = 0; nt < 6; ++nt) {
            int n = nt*8 + gid;
            uint32_t bh0 = Bh[ tig   *BS_STRIDE + n];
            uint32_t bh1 = Bh[(tig+4)*BS_STRIDE + n];
            uint32_t bl0 = Bl[ tig   *BS_STRIDE + n];
            uint32_t bl1 = Bl[(tig+4)*BS_STRIDE + n];
            mma_bf16(d[nt], ah, bh0, bh1);
            mma_bf16(d[nt], ah, bl0, bl1);
            mma_bf16(d[nt], al, bh0, bh1);
        }
        __syncthreads();
    }

    // stage C into smem, then coalesced biased write-out
    float* Cs = smem;
    #pragma unroll
    for (int nt = 0; nt < 6; ++nt) {
        int col = nt*8 + tig*2;
        Cs[(wm + gid    )*NP + col    ] = d[nt][0];
        Cs[(wm + gid    )*NP + col + 1] = d[nt][1];
        Cs[(wm + gid + 8)*NP + col    ] = d[nt][2];
        Cs[(wm + gid + 8)*NP + col + 1] = d[nt][3];
    }
    __syncthreads();
    const float4* csts4 = (const float4*)(smem + 3968);
    float4* outBase = (float4*)(g_pk + (size_t)m0*NP);
    #pragma unroll
    for (int it = 0; it < 6; ++it) {
        int i = t + 128*it;              // 768 float4 total
        float4 v = ((const float4*)Cs)[i];
        float4 c = csts4[i % 12];
        v.x += c.x; v.y += c.y; v.z += c.z; v.w += c.w;
        outBase[i] = v;
    }
}

// ================= kernel 2: dedupe + routing (verified 16us version) =================
__global__ __launch_bounds__(256) void route_kernel(
    const int* __restrict__ pts,
    const float* __restrict__ Wv,       // [258,16] (rel rows 256,257)
    const float* __restrict__ Wl,
    const float* __restrict__ bl,
    float* __restrict__ out)
{
    __shared__ unsigned bitmap[NPIX/32];
    __shared__ int counts[NPIX/32];
    __shared__ int offs[NPIX/32 + 1];
    __shared__ unsigned short cells[NPTS];
    __shared__ int sumY, sumX;
    __shared__ float scores[NCAPS][NPTS];
    __shared__ float vmatS[DV][NPTS];
    __shared__ float qwy[NCAPS], qwx[NCAPS];
    __shared__ float relVy[DV], relVx[DV], Wls[DV];

    int t  = threadIdx.x;
    int bi = blockIdx.x;
    const int* pbase = pts + (size_t)bi*2*NPTS;

    if (t < NPIX/32) bitmap[t] = 0u;
    if (t < NCAPS) { qwy[t] = g_QW[t*258 + 256]; qwx[t] = g_QW[t*258 + 257]; }
    if (t < DV) { relVy[t] = Wv[256*DV + t]; relVx[t] = Wv[257*DV + t]; Wls[t] = Wl[t]; }
    if (t == 0) { sumY = 0; sumX = 0; }
    __syncthreads();

    {
        int y = pbase[t] >> 4;
        int x = pbase[NPTS + t] >> 4;
        int key = y*WFD + x;
        atomicOr(&bitmap[key >> 5], 1u << (key & 31));
    }
    __syncthreads();
    if (t < NPIX/32) counts[t] = __popc(bitmap[t]);
    __syncthreads();
    if (t < 32) {
        int c0 = counts[t*4], c1 = counts[t*4+1], c2 = counts[t*4+2], c3 = counts[t*4+3];
        int s = c0 + c1 + c2 + c3;
        int run = s;
        #pragma unroll
        for (int off = 1; off < 32; off <<= 1) {
            int v = __shfl_up_sync(0xffffffffu, run, off);
            if (t >= off) run += v;
        }
        int excl = run - s;
        offs[t*4]   = excl;
        offs[t*4+1] = excl + c0;
        offs[t*4+2] = excl + c0 + c1;
        offs[t*4+3] = excl + c0 + c1 + c2;
        if (t == 31) offs[128] = run;
    }
    __syncthreads();
    if (t < NPIX/32) {
        unsigned bits = bitmap[t];
        int idx = offs[t];
        int sy = 0, sx = 0;
        while (bits) {
            int bpos = __ffs(bits) - 1;
            bits &= bits - 1;
            int cell = t*32 + bpos;
            cells[idx++] = (unsigned short)cell;
            sy += cell >> 6;
            sx += cell & 63;
        }
        if (counts[t]) { atomicAdd(&sumY, sy); atomicAdd(&sumX, sx); }
    }
    __syncthreads();

    int U = offs[NPIX/32];
    float nfl = (float)(U > 0 ? U : 1);
    float meanY = (float)sumY / nfl;
    float meanX = (float)sumX / nfl;

    if (t < U) {
        int cell = cells[t];
        const float4* pk4 = (const float4*)&g_pk[((size_t)(bi >> 5)*NPIX + cell)*NP];
        float4 q[9];
        #pragma unroll
        for (int i = 0; i < 9; ++i) q[i] = pk4[i];
        const float* pk = (const float*)q;

        float ry = ((float)(cell >> 6) - meanY) * (1.f/HFD);
        float rx = ((float)(cell & 63) - meanX) * (1.f/WFD);
        float act = 1.f/(1.f + expf(-pk[19]));
        float la  = logf(act + 1e-6f);
        #pragma unroll
        for (int c = 0; c < NCAPS; ++c)
            scores[c][t] = pk[c] + ry*qwy[c] + rx*qwx[c] + la;
        #pragma unroll
        for (int dd = 0; dd < DV; ++dd)
            vmatS[dd][t] = pk[20 + dd] + ry*relVy[dd] + rx*relVx[dd];
    }
    __syncthreads();

    int warp = t >> 5, lane = t & 31;
    for (int c = warp; c < NCAPS; c += 8) {
        float mx = -1e30f;
        for (int j = lane; j < U; j += 32) mx = fmaxf(mx, scores[c][j]);
        #pragma unroll
        for (int off = 16; off; off >>= 1) mx = fmaxf(mx, __shfl_xor_sync(0xffffffffu, mx, off));
        float se = 0.f;
        float acc[DV];
        #pragma unroll
        for (int dd = 0; dd < DV; ++dd) acc[dd] = 0.f;
        for (int j = lane; j < U; j += 32) {
            float e = expf(scores[c][j] - mx);
            se += e;
            #pragma unroll
            for (int dd = 0; dd < DV; ++dd) acc[dd] += e*vmatS[dd][j];
        }
        #pragma unroll
        for (int off = 16; off; off >>= 1) {
            se += __shfl_xor_sync(0xffffffffu, se, off);
            #pragma unroll
            for (int dd = 0; dd < DV; ++dd) acc[dd] += __shfl_xor_sync(0xffffffffu, acc[dd], off);
        }
        if (lane == 0) {
            float o = bl[0];
            float inv = 1.f/se;
            #pragma unroll
            for (int dd = 0; dd < DV; ++dd) o += (acc[dd]*inv)*Wls[dd];
            out[bi*NCAPS + c] = 1.f/(1.f + expf(-o));
        }
    }
}

extern "C" void kernel_launch(void* const* d_in, const int* in_sizes, int n_in,
                              void* d_out, int out_size) {
    const float* feat = (const float*)d_in[0];
    const float* Wp   = (const float*)d_in[1];
    const float* bp   = (const float*)d_in[2];
    const float* Wa   = (const float*)d_in[3];
    const float* ba   = (const float*)d_in[4];
    const float* Q    = (const float*)d_in[5];
    const float* Wk   = (const float*)d_in[6];
    const float* bk   = (const float*)d_in[7];
    const float* Wv   = (const float*)d_in[8];
    const float* bv   = (const float*)d_in[9];
    const float* Wl   = (const float*)d_in[10];
    const float* bl   = (const float*)d_in[11];
    const int*   pts  = (const int*)d_in[12];
    float* out = (float*)d_out;

    qw_kernel<<<(NCAPS*258 + 255)/256, 256>>>(Q, Wk);
    fold_kernel<<<CIN/2, 96>>>(Wp, Wa, Wv);
    const_kernel<<<1, NP>>>(bp, ba, Q, bk, Wv, bv);
    gemm_kernel<<<(BATCH*NPIX)/BM, 128>>>(feat);
    route_kernel<<<BATCH*NINST, 256>>>(pts, Wv, Wl, bl, out);
}

// round 7
// speedup vs baseline: 2.7795x; 1.1902x over previous
#include <cuda_runtime.h>
#include <cuda_bf16.h>
#include <math.h>
#include <stdint.h>

#define HFD 64
#define WFD 64
#define CIN 1280
#define CCAP 256
#define NCAPS 19
#define DK 64
#define DV 16
#define NP 48              // 0..18 score-base, 19 act-logit, 20..35 V, 36..47 zero pad
#define BATCH 8
#define NINST 32
#define NPTS 256
#define NPIX (HFD*WFD)     // 4096

// ---- device scratch (no cudaMalloc allowed) ----
__device__ float    g_QW[NCAPS*258];          // 0.125 * Q @ Wk^T   [19,258]
__device__ float    g_W2[CCAP*NP];            // fold RHS [256 x 48]
__device__ uint32_t g_Wbh[(CIN/2)*NP];        // folded weights, bf16 hi, packed k-pairs
__device__ uint32_t g_Wbl[(CIN/2)*NP];        // bf16 lo residual, packed k-pairs
__device__ float    g_const[NP];
__device__ float    g_pk[BATCH*NPIX*NP];      // 6.3 MB

__device__ __forceinline__ uint32_t packbf2(float x, float y) {
    __nv_bfloat162 h = __floats2bfloat162_rn(x, y);
    return *(uint32_t*)&h;
}

// ============ kernel A: QW = 0.125*Q@Wk^T [19x258], plus W2 operand [256x48] ============
__global__ void qw_kernel(const float* __restrict__ Q, const float* __restrict__ Wk,
                          const float* __restrict__ Wv) {
    int gtid = blockIdx.x * 256 + threadIdx.x;     // grid 20 -> 5120 threads
    if (gtid < NCAPS*258) {
        int c = gtid / 258, j = gtid % 258;
        float s = 0.f;
        #pragma unroll 8
        for (int o = 0; o < DK; ++o) s += Q[c*DK + o] * Wk[j*DK + o];
        s *= 0.125f;
        g_QW[gtid] = s;
        if (j < CCAP) g_W2[j*NP + c] = s;          // transpose into W2 cols 0..18
    }
    // W2 cols 19..47: 19 & 36..47 -> 0, 20..35 -> Wv
    for (int i = gtid; i < CCAP*29; i += 5120) {
        int j = i / 29, col = 19 + i % 29;
        float v = 0.f;
        if (col >= 20 && col < 20 + DV) v = Wv[j*DV + (col - 20)];
        g_W2[j*NP + col] = v;
    }
}

// ============ kernel B: Wf[1280x48] = Wp^T @ W2, coalesced tiled, bf16 hi/lo pairs ============
// grid 20 (64 channels each); 256 threads = 32 channel-pairs x 8 col-groups (6 cols each)
__global__ __launch_bounds__(256) void fold_kernel(const float* __restrict__ Wp,
                                                   const float* __restrict__ Wa) {
    __shared__ float wpS[64*64];   // [j][c]
    __shared__ float w2S[64*NP];   // [j][col]
    int t = threadIdx.x;
    int c0 = blockIdx.x * 64;
    int cp = t & 31;               // channel pair 0..31
    int tq = t >> 5;               // 0..7
    float acc0[6], acc1[6];
    #pragma unroll
    for (int r = 0; r < 6; ++r) { acc0[r] = 0.f; acc1[r] = 0.f; }

    for (int j0 = 0; j0 < CCAP; j0 += 64) {
        #pragma unroll
        for (int r = 0; r < 4; ++r) {
            int i = t + 256*r;                 // 1024 float4
            int jj = i >> 4, c4 = (i & 15) * 4;
            *(float4*)&wpS[jj*64 + c4] = *(const float4*)&Wp[(size_t)(j0+jj)*CIN + c0 + c4];
        }
        #pragma unroll
        for (int r = 0; r < 3; ++r) {
            int i = t + 256*r;                 // 768 float4
            int jj = i / 12, c4 = (i % 12) * 4;
            *(float4*)&w2S[jj*NP + c4] = *(const float4*)&g_W2[(j0+jj)*NP + c4];
        }
        __syncthreads();
        #pragma unroll 4
        for (int jj = 0; jj < 64; ++jj) {
            float a0 = wpS[jj*64 + 2*cp];
            float a1 = wpS[jj*64 + 2*cp + 1];
            #pragma unroll
            for (int r = 0; r < 6; ++r) {
                float w = w2S[jj*NP + tq*6 + r];
                acc0[r] += a0*w;
                acc1[r] += a1*w;
            }
        }
        __syncthreads();
    }
    int c = c0 + 2*cp;
    #pragma unroll
    for (int r = 0; r < 6; ++r) {
        int col = tq*6 + r;
        float s0 = (col == NCAPS) ? Wa[c]     : acc0[r];
        float s1 = (col == NCAPS) ? Wa[c + 1] : acc1[r];
        __nv_bfloat162 h = __floats2bfloat162_rn(s0, s1);
        g_Wbh[(c >> 1)*NP + col] = *(uint32_t*)&h;
        g_Wbl[(c >> 1)*NP + col] =
            packbf2(s0 - __bfloat162float(h.x), s1 - __bfloat162float(h.y));
    }
}

// ============ kernel C: folded biases (warp-parallel) ============
__global__ __launch_bounds__(256) void const_kernel(
    const float* __restrict__ bp, const float* __restrict__ ba,
    const float* __restrict__ Q,  const float* __restrict__ bk,
    const float* __restrict__ Wv, const float* __restrict__ bv) {
    int t = threadIdx.x, w = t >> 5, lane = t & 31;
    for (int o = w; o < NP; o += 8) {
        float s = 0.f;
        if (o < NCAPS) {
            for (int j = lane; j < CCAP; j += 32) s += bp[j] * g_QW[o*258 + j];
            for (int j = lane; j < DK; j += 32)   s += 0.125f * Q[o*DK + j] * bk[j];
        } else if (o >= 20 && o < 20 + DV) {
            for (int j = lane; j < CCAP; j += 32) s += bp[j] * Wv[j*DV + (o - 20)];
        }
        #pragma unroll
        for (int off = 16; off; off >>= 1) s += __shfl_xor_sync(0xffffffffu, s, off);
        if (lane == 0) {
            if (o == NCAPS) s = ba[0];
            else if (o >= 20 && o < 20 + DV) s += bv[o - 20];
            g_const[o] = s;
        }
    }
}

// ============ GEMM: pk[32768x48] = feat @ Wfold, 3xBF16 mma, BM=32, grid 1024 ============
#define BM 32
#define BK 16
#define AS_STRIDE 36
#define BS_STRIDE 56
#define NKCH (CIN/BK)      // 80

#define CP_ASYNC16(dst_s32, src) \
    asm volatile("cp.async.cg.shared.global [%0], [%1], 16;\n" :: "r"(dst_s32), "l"(src))
#define CP_COMMIT() asm volatile("cp.async.commit_group;\n")

__device__ __forceinline__ void mma_bf16(float* d, const uint32_t* a, uint32_t b0, uint32_t b1) {
    asm volatile(
        "mma.sync.aligned.m16n8k16.row.col.f32.bf16.bf16.f32 "
        "{%0,%1,%2,%3},{%4,%5,%6,%7},{%8,%9},{%0,%1,%2,%3};\n"
        : "+f"(d[0]), "+f"(d[1]), "+f"(d[2]), "+f"(d[3])
        : "r"(a[0]), "r"(a[1]), "r"(a[2]), "r"(a[3]), "r"(b0), "r"(b1));
}

// smem floats: As 2x(16x36)=1152 | Bh 2x448 @1152 | Bl 2x448 @2048 | csts 48 @2944
// epilogue: Cs 32x48=1536 reuses [0,1536)
__global__ __launch_bounds__(128) void gemm_kernel(const float* __restrict__ feat) {
    __shared__ __align__(16) float smem[2992];
    int t = threadIdx.x;
    int m0 = blockIdx.x * BM;
    int b  = m0 / NPIX;
    int pix0 = m0 % NPIX;
    const float* aBase = feat + (size_t)b*CIN*NPIX + pix0;

    if (t < NP) smem[2944 + t] = g_const[t];

    int lane = t & 31, w = t >> 5;
    int gid = lane >> 2, tig = lane & 3;
    int wm = (w & 1) * 16;           // 2 M-groups
    int wn = (w >> 1) * 24;          // 2 N-groups (24 cols = 3 n-tiles)

    uint32_t s_as = (uint32_t)__cvta_generic_to_shared(smem);
    uint32_t s_bh = s_as + 1152*4;
    uint32_t s_bl = s_as + 2048*4;

    int a_kk = t >> 3;               // 0..15, one float4 each
    int a_m0 = (t & 7) * 4;
    int b_kp = t / 12;               // 0..7 (t<96)
    int b_n0 = (t % 12) * 4;

#define LOAD_STAGE(p, k0)                                                            \
    do {                                                                             \
        CP_ASYNC16(s_as + ((p)*576 + a_kk*AS_STRIDE + a_m0)*4,                       \
                   aBase + (size_t)((k0)+a_kk)*NPIX + a_m0);                         \
        if (t < 96) {                                                                \
            CP_ASYNC16(s_bh + ((p)*448 + b_kp*BS_STRIDE + b_n0)*4,                   \
                       &g_Wbh[((k0)/2 + b_kp)*NP + b_n0]);                           \
            CP_ASYNC16(s_bl + ((p)*448 + b_kp*BS_STRIDE + b_n0)*4,                   \
                       &g_Wbl[((k0)/2 + b_kp)*NP + b_n0]);                           \
        }                                                                            \
        CP_COMMIT();                                                                 \
    } while (0)

    LOAD_STAGE(0, 0);

    float d[3][4];
    #pragma unroll
    for (int nt = 0; nt < 3; ++nt)
        #pragma unroll
        for (int i = 0; i < 4; ++i) d[nt][i] = 0.f;

    for (int kc = 0; kc < NKCH; ++kc) {
        if (kc + 1 < NKCH) {
            LOAD_STAGE((kc+1) & 1, (kc+1)*BK);
            asm volatile("cp.async.wait_group 1;\n");
        } else {
            asm volatile("cp.async.wait_group 0;\n");
        }
        __syncthreads();

        const float*    As_ = smem + (kc&1)*576;
        const uint32_t* Bh  = (const uint32_t*)(smem + 1152) + (kc&1)*448;
        const uint32_t* Bl  = (const uint32_t*)(smem + 2048) + (kc&1)*448;

        int m = wm + gid;
        float L00 = As_[(2*tig  )*AS_STRIDE + m];
        float L01 = As_[(2*tig+1)*AS_STRIDE + m];
        float L08 = As_[(2*tig+8)*AS_STRIDE + m];
        float L09 = As_[(2*tig+9)*AS_STRIDE + m];
        float M00 = As_[(2*tig  )*AS_STRIDE + m + 8];
        float M01 = As_[(2*tig+1)*AS_STRIDE + m + 8];
        float M08 = As_[(2*tig+8)*AS_STRIDE + m + 8];
        float M09 = As_[(2*tig+9)*AS_STRIDE + m + 8];

        uint32_t ah[4], al[4];
        {
            __nv_bfloat162 h;
            h = __floats2bfloat162_rn(L00, L01); ah[0] = *(uint32_t*)&h;
            al[0] = packbf2(L00 - __bfloat162float(h.x), L01 - __bfloat162float(h.y));
            h = __floats2bfloat162_rn(M00, M01); ah[1] = *(uint32_t*)&h;
            al[1] = packbf2(M00 - __bfloat162float(h.x), M01 - __bfloat162float(h.y));
            h = __floats2bfloat162_rn(L08, L09); ah[2] = *(uint32_t*)&h;
            al[2] = packbf2(L08 - __bfloat162float(h.x), L09 - __bfloat162float(h.y));
            h = __floats2bfloat162_rn(M08, M09); ah[3] = *(uint32_t*)&h;
            al[3] = packbf2(M08 - __bfloat162float(h.x), M09 - __bfloat162float(h.y));
        }

        #pragma unroll
        for (int nt = 0; nt < 3; ++nt) {
            int n = wn + nt*8 + gid;
            uint32_t bh0 = Bh[ tig   *BS_STRIDE + n];
            uint32_t bh1 = Bh[(tig+4)*BS_STRIDE + n];
            uint32_t bl0 = Bl[ tig   *BS_STRIDE + n];
            uint32_t bl1 = Bl[(tig+4)*BS_STRIDE + n];
            mma_bf16(d[nt], ah, bh0, bh1);
            mma_bf16(d[nt], ah, bl0, bl1);
            mma_bf16(d[nt], al, bh0, bh1);
        }
        __syncthreads();
    }

    // stage C into smem, then coalesced biased write-out
    float* Cs = smem;
    #pragma unroll
    for (int nt = 0; nt < 3; ++nt) {
        int col = wn + nt*8 + tig*2;
        Cs[(wm + gid    )*NP + col    ] = d[nt][0];
        Cs[(wm + gid    )*NP + col + 1] = d[nt][1];
        Cs[(wm + gid + 8)*NP + col    ] = d[nt][2];
        Cs[(wm + gid + 8)*NP + col + 1] = d[nt][3];
    }
    __syncthreads();
    const float4* csts4 = (const float4*)(smem + 2944);
    float4* outBase = (float4*)(g_pk + (size_t)m0*NP);
    #pragma unroll
    for (int it = 0; it < 3; ++it) {
        int i = t + 128*it;              // 384 float4 total
        float4 v = ((const float4*)Cs)[i];
        float4 c = csts4[i % 12];
        v.x += c.x; v.y += c.y; v.z += c.z; v.w += c.w;
        outBase[i] = v;
    }
}

// ============ route: dedupe + softmax routing (verified) ============
__global__ __launch_bounds__(256) void route_kernel(
    const int* __restrict__ pts,
    const float* __restrict__ Wv,
    const float* __restrict__ Wl,
    const float* __restrict__ bl,
    float* __restrict__ out)
{
    __shared__ unsigned bitmap[NPIX/32];
    __shared__ int counts[NPIX/32];
    __shared__ int offs[NPIX/32 + 1];
    __shared__ unsigned short cells[NPTS];
    __shared__ int sumY, sumX;
    __shared__ float scores[NCAPS][NPTS];
    __shared__ float vmatS[DV][NPTS];
    __shared__ float qwy[NCAPS], qwx[NCAPS];
    __shared__ float relVy[DV], relVx[DV], Wls[DV];

    int t  = threadIdx.x;
    int bi = blockIdx.x;
    const int* pbase = pts + (size_t)bi*2*NPTS;

    if (t < NPIX/32) bitmap[t] = 0u;
    if (t < NCAPS) { qwy[t] = g_QW[t*258 + 256]; qwx[t] = g_QW[t*258 + 257]; }
    if (t < DV) { relVy[t] = Wv[256*DV + t]; relVx[t] = Wv[257*DV + t]; Wls[t] = Wl[t]; }
    if (t == 0) { sumY = 0; sumX = 0; }
    __syncthreads();

    {
        int y = pbase[t] >> 4;
        int x = pbase[NPTS + t] >> 4;
        int key = y*WFD + x;
        atomicOr(&bitmap[key >> 5], 1u << (key & 31));
    }
    __syncthreads();
    if (t < NPIX/32) counts[t] = __popc(bitmap[t]);
    __syncthreads();
    if (t < 32) {
        int c0 = counts[t*4], c1 = counts[t*4+1], c2 = counts[t*4+2], c3 = counts[t*4+3];
        int s = c0 + c1 + c2 + c3;
        int run = s;
        #pragma unroll
        for (int off = 1; off < 32; off <<= 1) {
            int v = __shfl_up_sync(0xffffffffu, run, off);
            if (t >= off) run += v;
        }
        int excl = run - s;
        offs[t*4]   = excl;
        offs[t*4+1] = excl + c0;
        offs[t*4+2] = excl + c0 + c1;
        offs[t*4+3] = excl + c0 + c1 + c2;
        if (t == 31) offs[128] = run;
    }
    __syncthreads();
    if (t < NPIX/32) {
        unsigned bits = bitmap[t];
        int idx = offs[t];
        int sy = 0, sx = 0;
        while (bits) {
            int bpos = __ffs(bits) - 1;
            bits &= bits - 1;
            int cell = t*32 + bpos;
            cells[idx++] = (unsigned short)cell;
            sy += cell >> 6;
            sx += cell & 63;
        }
        if (counts[t]) { atomicAdd(&sumY, sy); atomicAdd(&sumX, sx); }
    }
    __syncthreads();

    int U = offs[NPIX/32];
    float nfl = (float)(U > 0 ? U : 1);
    float meanY = (float)sumY / nfl;
    float meanX = (float)sumX / nfl;

    if (t < U) {
        int cell = cells[t];
        const float4* pk4 = (const float4*)&g_pk[((size_t)(bi >> 5)*NPIX + cell)*NP];
        float4 q[9];
        #pragma unroll
        for (int i = 0; i < 9; ++i) q[i] = pk4[i];
        const float* pk = (const float*)q;

        float ry = ((float)(cell >> 6) - meanY) * (1.f/HFD);
        float rx = ((float)(cell & 63) - meanX) * (1.f/WFD);
        float act = 1.f/(1.f + expf(-pk[19]));
        float la  = logf(act + 1e-6f);
        #pragma unroll
        for (int c = 0; c < NCAPS; ++c)
            scores[c][t] = pk[c] + ry*qwy[c] + rx*qwx[c] + la;
        #pragma unroll
        for (int dd = 0; dd < DV; ++dd)
            vmatS[dd][t] = pk[20 + dd] + ry*relVy[dd] + rx*relVx[dd];
    }
    __syncthreads();

    int warp = t >> 5, lane = t & 31;
    for (int c = warp; c < NCAPS; c += 8) {
        float mx = -1e30f;
        for (int j = lane; j < U; j += 32) mx = fmaxf(mx, scores[c][j]);
        #pragma unroll
        for (int off = 16; off; off >>= 1) mx = fmaxf(mx, __shfl_xor_sync(0xffffffffu, mx, off));
        float se = 0.f;
        float acc[DV];
        #pragma unroll
        for (int dd = 0; dd < DV; ++dd) acc[dd] = 0.f;
        for (int j = lane; j < U; j += 32) {
            float e = expf(scores[c][j] - mx);
            se += e;
            #pragma unroll
            for (int dd = 0; dd < DV; ++dd) acc[dd] += e*vmatS[dd][j];
        }
        #pragma unroll
        for (int off = 16; off; off >>= 1) {
            se += __shfl_xor_sync(0xffffffffu, se, off);
            #pragma unroll
            for (int dd = 0; dd < DV; ++dd) acc[dd] += __shfl_xor_sync(0xffffffffu, acc[dd], off);
        }
        if (lane == 0) {
            float o = bl[0];
            float inv = 1.f/se;
            #pragma unroll
            for (int dd = 0; dd < DV; ++dd) o += (acc[dd]*inv)*Wls[dd];
            out[bi*NCAPS + c] = 1.f/(1.f + expf(-o));
        }
    }
}

extern "C" void kernel_launch(void* const* d_in, const int* in_sizes, int n_in,
                              void* d_out, int out_size) {
    const float* feat = (const float*)d_in[0];
    const float* Wp   = (const float*)d_in[1];
    const float* bp   = (const float*)d_in[2];
    const float* Wa   = (const float*)d_in[3];
    const float* ba   = (const float*)d_in[4];
    const float* Q    = (const float*)d_in[5];
    const float* Wk   = (const float*)d_in[6];
    const float* bk   = (const float*)d_in[7];
    const float* Wv   = (const float*)d_in[8];
    const float* bv   = (const float*)d_in[9];
    const float* Wl   = (const float*)d_in[10];
    const float* bl   = (const float*)d_in[11];
    const int*   pts  = (const int*)d_in[12];
    float* out = (float*)d_out;

    qw_kernel<<<20, 256>>>(Q, Wk, Wv);
    fold_kernel<<<CIN/64, 256>>>(Wp, Wa);
    const_kernel<<<1, 256>>>(bp, ba, Q, bk, Wv, bv);
    gemm_kernel<<<(BATCH*NPIX)/BM, 128>>>(feat);
    route_kernel<<<BATCH*NINST, 256>>>(pts, Wv, Wl, bl, out);
}